// round 9
// baseline (speedup 1.0000x reference)
#include <cuda_runtime.h>
#include <cuda_bf16.h>
#include <math.h>
#include <stdint.h>

#define E_EDGES 400000
#define NGROUPS 25000

// ===========================================================================
// PTX helpers (sm_80-class only — toolchain targets plain sm_103, no tcgen05)
// ===========================================================================
__device__ __forceinline__ uint32_t smem_u32(const void* p) {
    uint32_t a;
    asm("{ .reg .u64 t; cvta.to.shared.u64 t, %1; cvt.u32.u64 %0, t; }"
        : "=r"(a) : "l"(p));
    return a;
}

#define CP_ASYNC16(sm, gm) \
    asm volatile("cp.async.cg.shared.global [%0], [%1], 16;" \
        :: "r"(sm), "l"(gm) : "memory")
#define CP_COMMIT() asm volatile("cp.async.commit_group;" ::: "memory")
#define CP_WAIT(n)  asm volatile("cp.async.wait_group %0;" :: "n"(n) : "memory")

__device__ __forceinline__ void ldsm_x4(uint32_t* d, uint32_t addr) {
    asm volatile("ldmatrix.sync.aligned.m8n8.x4.shared.b16 {%0,%1,%2,%3}, [%4];"
        : "=r"(d[0]), "=r"(d[1]), "=r"(d[2]), "=r"(d[3]) : "r"(addr));
}

#define MMA16816(d, a, b) \
    asm volatile("mma.sync.aligned.m16n8k16.row.col.f32.bf16.bf16.f32 " \
        "{%0,%1,%2,%3}, {%4,%5,%6,%7}, {%8,%9}, {%0,%1,%2,%3};" \
        : "+f"((d)[0]), "+f"((d)[1]), "+f"((d)[2]), "+f"((d)[3]) \
        : "r"((a)[0]), "r"((a)[1]), "r"((a)[2]), "r"((a)[3]), \
          "r"((b)[0]), "r"((b)[1]))

// SW64 swizzle for 64-byte rows (BK=32 bf16)
__device__ __forceinline__ uint32_t sw(uint32_t off) {
    return off ^ ((off >> 3) & 0x30);
}

// ===========================================================================
// Scratch globals (no cudaMalloc allowed)
// ===========================================================================
__device__ __nv_bfloat16 g_hiA[(size_t)E_EDGES * 256];
__device__ __nv_bfloat16 g_loA[(size_t)E_EDGES * 256];
__device__ __nv_bfloat16 g_hiB[(size_t)E_EDGES * 256];
__device__ __nv_bfloat16 g_loB[(size_t)E_EDGES * 256];
__device__ float g_q  [(size_t)E_EDGES * 32];
__device__ float g_xnk[(size_t)E_EDGES * 96];

__device__ float g_W2q [256 * 32];   // W2 @ Wqk  (fp32, [k][n])
__device__ float g_Wcat[256 * 96];   // [W2 | W2@Wk] (fp32, [k][n])
// Transposed + split weights, [n][k] layout (K contiguous)
__device__ __nv_bfloat16 g_W0t_hi[256 * 256], g_W0t_lo[256 * 256];
__device__ __nv_bfloat16 g_W1t_hi[256 * 256], g_W1t_lo[256 * 256];
__device__ __nv_bfloat16 g_W2qt_hi[32 * 256], g_W2qt_lo[32 * 256];
__device__ __nv_bfloat16 g_Wct_hi[96 * 256],  g_Wct_lo[96 * 256];

__device__ __forceinline__ void split2(float v, __nv_bfloat16& h, __nv_bfloat16& l) {
    h = __float2bfloat16_rn(v);
    l = __float2bfloat16_rn(v - __bfloat162float(h));
}

// ===========================================================================
// prep1: fold head projections: g_W2q = W2@Wqk, g_Wcat = [W2 | W2@Wk]
// ===========================================================================
__global__ void prep_fold(const float* __restrict__ W2,
                          const float* __restrict__ Wqk,
                          const float* __restrict__ Wk) {
    __shared__ float sQ[64 * 32];
    __shared__ float sK[64 * 32];
    int tid = threadIdx.x;
    for (int i = tid; i < 64 * 32; i += 256) { sQ[i] = Wqk[i]; sK[i] = Wk[i]; }
    __syncthreads();
    int r = tid;
    float w2r[64];
#pragma unroll
    for (int j = 0; j < 64; ++j) w2r[j] = W2[r * 64 + j];
#pragma unroll 4
    for (int c = 0; c < 32; ++c) {
        float aq = 0.f, ak = 0.f;
#pragma unroll
        for (int j = 0; j < 64; ++j) {
            aq = fmaf(w2r[j], sQ[j * 32 + c], aq);
            ak = fmaf(w2r[j], sK[j * 32 + c], ak);
        }
        g_W2q[r * 32 + c]       = aq;
        g_Wcat[r * 96 + 64 + c] = ak;
    }
#pragma unroll
    for (int j = 0; j < 64; ++j) g_Wcat[r * 96 + j] = w2r[j];
}

// ===========================================================================
// prep2: transpose to [n][k] and split all GEMM weights to bf16 hi/lo
// ===========================================================================
__global__ void prep_transpose_split(const float* __restrict__ W0,
                                     const float* __restrict__ W1) {
    int t = blockIdx.x * 256 + threadIdx.x;
    int o = t >> 8, i = t & 255;
    __nv_bfloat16 h, l;
    split2(W0[i * 256 + o], h, l);  g_W0t_hi[t] = h;  g_W0t_lo[t] = l;
    split2(W1[i * 256 + o], h, l);  g_W1t_hi[t] = h;  g_W1t_lo[t] = l;
    if (o < 32) { split2(g_W2q[i * 32 + o], h, l);  g_W2qt_hi[t] = h; g_W2qt_lo[t] = l; }
    if (o < 96) { split2(g_Wcat[i * 96 + o], h, l); g_Wct_hi[t] = h;  g_Wct_lo[t] = l; }
}

// ===========================================================================
// HMMA GEMM, bf16x3: C = Ah*Bh + Al*Bh + Ah*Bl.
// BM=128, BK=32, 8 K-chunks. THREE smem stages, loads issued 2 chunks ahead,
// ONE __syncthreads per chunk:
//   iter c:  CP_WAIT(chunk c landed) -> sync -> issue loads c+2 -> compute c
// Buffer (c+2)%3 == (c-1)%3 is free: every warp passed compute(c-1) before
// the sync. 256 threads = 8 warps (4M x 2N). NCTA = CTAs/SM via launch_bounds.
// FP32A: A fp32 in gmem, LDG prefetch (after sync, hidden under MMAs),
//        split + STS at iteration end.
// SPLIT_RELU: relu + re-split hi/lo bf16 (width 256). Else fp32 store (W_OUT).
// ===========================================================================
template <int BN, int W_OUT, bool SPLIT_RELU, bool FP32A, int NCTA>
__global__ void __launch_bounds__(256, NCTA)
hmma_gemm(const void* __restrict__ Ah_, const __nv_bfloat16* __restrict__ Al,
          const __nv_bfloat16* __restrict__ Bh, const __nv_bfloat16* __restrict__ Bl,
          void* __restrict__ outHi, __nv_bfloat16* __restrict__ outLo) {
    constexpr int NB    = BN / 16;           // n8-tiles per warp (warp covers BN/2)
    constexpr int A_CH  = 128 * 64;          // bytes per A split per chunk
    constexpr int B_CH  = BN * 64;
    constexpr int STAGE = 2 * A_CH + 2 * B_CH;

    extern __shared__ char smem[];
    const uint32_t s0 = smem_u32(smem);

    const int tid  = threadIdx.x;
    const int lane = tid & 31;
    const int wid  = tid >> 5;
    const int m0w  = (wid & 3) * 32;
    const int n0w  = (wid >> 2) * (BN / 2);
    const int row0 = blockIdx.x * 128;
    const int col0 = blockIdx.y * BN;

    const float* Afp = (const float*)Ah_;
    const __nv_bfloat16* Ah = (const __nv_bfloat16*)Ah_;

    float acc[2][NB][4];
#pragma unroll
    for (int mi = 0; mi < 2; ++mi)
#pragma unroll
        for (int ni = 0; ni < NB; ++ni)
#pragma unroll
            for (int v = 0; v < 4; ++v) acc[mi][ni][v] = 0.f;

    float4 pf[4];  // FP32A prefetch: 128x32 fp32 chunk = 4 float4/thread

    auto loadB = [&](int c, int buf) {
        const int kk = c << 5;
#pragma unroll
        for (int i = tid; i < 2 * BN * 4; i += 256) {
            int sp = i / (BN * 4), idx = i % (BN * 4), n = idx >> 2, g = idx & 3;
            const __nv_bfloat16* src =
                (sp ? Bl : Bh) + (size_t)(col0 + n) * 256 + kk + g * 8;
            CP_ASYNC16(s0 + buf * STAGE + 2 * A_CH + sp * B_CH + sw(n * 64 + g * 16), src);
        }
    };
    auto loadA_cp = [&](int c, int buf) {
        const int kk = c << 5;
#pragma unroll
        for (int i = tid; i < 1024; i += 256) {
            int sp = i >> 9, idx = i & 511, r = idx >> 2, g = idx & 3;
            const __nv_bfloat16* src =
                (sp ? Al : Ah) + (size_t)(row0 + r) * 256 + kk + g * 8;
            CP_ASYNC16(s0 + buf * STAGE + sp * A_CH + sw(r * 64 + g * 16), src);
        }
    };
    auto ldA_f32 = [&](int c) {
        const int kk = c << 5;
#pragma unroll
        for (int j = 0; j < 4; ++j) {
            int f4 = tid + 256 * j;
            int r = f4 >> 3, c4 = f4 & 7;
            pf[j] = *(const float4*)(Afp + (size_t)(row0 + r) * 256 + kk + c4 * 4);
        }
    };
    auto stA_f32 = [&](int buf) {
#pragma unroll
        for (int j = 0; j < 4; ++j) {
            int f4 = tid + 256 * j;
            int r = f4 >> 3, c4 = f4 & 7;
            __nv_bfloat16 h0, l0, h1, l1, h2, l2, h3, l3;
            split2(pf[j].x, h0, l0); split2(pf[j].y, h1, l1);
            split2(pf[j].z, h2, l2); split2(pf[j].w, h3, l3);
            uint2 hw = make_uint2(
                (uint32_t)__bfloat16_as_ushort(h0) | ((uint32_t)__bfloat16_as_ushort(h1) << 16),
                (uint32_t)__bfloat16_as_ushort(h2) | ((uint32_t)__bfloat16_as_ushort(h3) << 16));
            uint2 lw = make_uint2(
                (uint32_t)__bfloat16_as_ushort(l0) | ((uint32_t)__bfloat16_as_ushort(l1) << 16),
                (uint32_t)__bfloat16_as_ushort(l2) | ((uint32_t)__bfloat16_as_ushort(l3) << 16));
            uint32_t off = buf * STAGE + sw(r * 64 + c4 * 8);
            *(uint2*)(smem + off)        = hw;
            *(uint2*)(smem + off + A_CH) = lw;
        }
    };

    // ---- prologue: stage chunks 0 and 1 ----
    if (FP32A) {
        ldA_f32(0); stA_f32(0);
        ldA_f32(1); stA_f32(1);
        loadB(0, 0); CP_COMMIT();
        loadB(1, 1); CP_COMMIT();
    } else {
        loadA_cp(0, 0); loadB(0, 0); CP_COMMIT();
        loadA_cp(1, 1); loadB(1, 1); CP_COMMIT();
    }

#pragma unroll 1
    for (int c = 0; c < 8; ++c) {
        if (c < 7) CP_WAIT(1); else CP_WAIT(0);   // chunk c resident
        __syncthreads();                           // the ONLY barrier per chunk

        if (c < 6) {                               // stage chunk c+2
            const int buf2 = (c + 2) % 3;
            if (FP32A) {
                ldA_f32(c + 2);                    // LDG latency hidden by MMAs
                loadB(c + 2, buf2);
            } else {
                loadA_cp(c + 2, buf2);
                loadB(c + 2, buf2);
            }
            CP_COMMIT();
        }

        const uint32_t st = s0 + (c % 3) * STAGE;
        const uint32_t da = st;
        const uint32_t db = st + 2 * A_CH;
#pragma unroll
        for (int ks = 0; ks < 2; ++ks) {
            uint32_t ah[2][4], al[2][4];
#pragma unroll
            for (int mi = 0; mi < 2; ++mi) {
                uint32_t aoff = sw((m0w + mi * 16 + (lane & 15)) * 64 +
                                   ks * 32 + (lane >> 4) * 16);
                ldsm_x4(ah[mi], da + aoff);
                ldsm_x4(al[mi], da + A_CH + aoff);
            }
#pragma unroll
            for (int np = 0; np < NB / 2; ++np) {
                uint32_t boff = sw((n0w + np * 16 + (lane >> 4) * 8 + (lane & 7)) * 64 +
                                   ks * 32 + ((lane >> 3) & 1) * 16);
                uint32_t bh4[4], bl4[4];
                ldsm_x4(bh4, db + boff);
                ldsm_x4(bl4, db + B_CH + boff);
#pragma unroll
                for (int mi = 0; mi < 2; ++mi) MMA16816(acc[mi][2 * np],     ah[mi], bh4);
#pragma unroll
                for (int mi = 0; mi < 2; ++mi) MMA16816(acc[mi][2 * np + 1], ah[mi], bh4 + 2);
#pragma unroll
                for (int mi = 0; mi < 2; ++mi) MMA16816(acc[mi][2 * np],     al[mi], bh4);
#pragma unroll
                for (int mi = 0; mi < 2; ++mi) MMA16816(acc[mi][2 * np + 1], al[mi], bh4 + 2);
#pragma unroll
                for (int mi = 0; mi < 2; ++mi) MMA16816(acc[mi][2 * np],     ah[mi], bl4);
#pragma unroll
                for (int mi = 0; mi < 2; ++mi) MMA16816(acc[mi][2 * np + 1], ah[mi], bl4 + 2);
            }
        }
        if (FP32A && c < 6) stA_f32((c + 2) % 3);  // STS for chunk c+2 (read 2 syncs later)
    }

    // ---- epilogue ----
    const int rbase = row0 + m0w + (lane >> 2);
#pragma unroll
    for (int mi = 0; mi < 2; ++mi) {
        const int r0 = rbase + mi * 16;
#pragma unroll
        for (int ni = 0; ni < NB; ++ni) {
            const int c = col0 + n0w + ni * 8 + (lane & 3) * 2;
            if (SPLIT_RELU) {
                __nv_bfloat16* hi = (__nv_bfloat16*)outHi;
#pragma unroll
                for (int h = 0; h < 2; ++h) {
                    float v0 = fmaxf(acc[mi][ni][2 * h],     0.f);
                    float v1 = fmaxf(acc[mi][ni][2 * h + 1], 0.f);
                    __nv_bfloat16 h0, l0, h1, l1;
                    split2(v0, h0, l0);
                    split2(v1, h1, l1);
                    size_t off = (size_t)(r0 + h * 8) * 256 + c;
                    *(uint32_t*)(hi + off)    = (uint32_t)__bfloat16_as_ushort(h0) |
                                                ((uint32_t)__bfloat16_as_ushort(h1) << 16);
                    *(uint32_t*)(outLo + off) = (uint32_t)__bfloat16_as_ushort(l0) |
                                                ((uint32_t)__bfloat16_as_ushort(l1) << 16);
                }
            } else {
                float* of = (float*)outHi;
                *(float2*)(of + (size_t)r0 * W_OUT + c) =
                    make_float2(acc[mi][ni][0], acc[mi][ni][1]);
                *(float2*)(of + (size_t)(r0 + 8) * W_OUT + c) =
                    make_float2(acc[mi][ni][2], acc[mi][ni][3]);
            }
        }
    }
}

// ===========================================================================
// Edge finalize: one warp per edge.
// ===========================================================================
__global__ void edge_finalize(const float* __restrict__ ppr_scores,
                              const int* __restrict__ ppr_idx,
                              float* __restrict__ out) {
    int gtid = blockIdx.x * blockDim.x + threadIdx.x;
    int edge = gtid >> 5;
    int lane = gtid & 31;
    if (edge >= E_EDGES) return;

    const float* xnk = g_xnk + (size_t)edge * 96;
    float p = g_q[(size_t)edge * 32 + lane] * xnk[64 + lane];
#pragma unroll
    for (int off = 16; off > 0; off >>= 1)
        p += __shfl_xor_sync(0xffffffffu, p, off);

    float s = ppr_scores[edge] / (1.f + expf(-p));
    int g = ppr_idx[edge];
    atomicAdd(&out[(size_t)g * 64 + lane],      xnk[lane]      * s);
    atomicAdd(&out[(size_t)g * 64 + 32 + lane], xnk[32 + lane] * s);
}

// ===========================================================================
// Launch sequence (graph-capturable)
// ===========================================================================
extern "C" void kernel_launch(void* const* d_in, const int* in_sizes, int n_in,
                              void* d_out, int out_size) {
    const float* source_attr   = (const float*)d_in[0];
    const float* neighbor_attr = (const float*)d_in[1];
    const float* ppr_scores    = (const float*)d_in[2];
    const int*   ppr_idx       = (const int*)  d_in[3];
    const float* W0  = (const float*)d_in[5];
    const float* W1  = (const float*)d_in[6];
    const float* W2  = (const float*)d_in[7];
    const float* Wqk = (const float*)d_in[8];
    const float* Wk  = (const float*)d_in[9];
    float* out = (float*)d_out;

    __nv_bfloat16 *hiA, *loA, *hiB, *loB;
    __nv_bfloat16 *w0h, *w0l, *w1h, *w1l, *w2qh, *w2ql, *wch, *wcl;
    float *qbuf, *xnk;
    cudaGetSymbolAddress((void**)&hiA, g_hiA);
    cudaGetSymbolAddress((void**)&loA, g_loA);
    cudaGetSymbolAddress((void**)&hiB, g_hiB);
    cudaGetSymbolAddress((void**)&loB, g_loB);
    cudaGetSymbolAddress((void**)&qbuf, g_q);
    cudaGetSymbolAddress((void**)&xnk,  g_xnk);
    cudaGetSymbolAddress((void**)&w0h, g_W0t_hi);
    cudaGetSymbolAddress((void**)&w0l, g_W0t_lo);
    cudaGetSymbolAddress((void**)&w1h, g_W1t_hi);
    cudaGetSymbolAddress((void**)&w1l, g_W1t_lo);
    cudaGetSymbolAddress((void**)&w2qh, g_W2qt_hi);
    cudaGetSymbolAddress((void**)&w2ql, g_W2qt_lo);
    cudaGetSymbolAddress((void**)&wch, g_Wct_hi);
    cudaGetSymbolAddress((void**)&wcl, g_Wct_lo);

    // dynamic smem: 3 stages x (2*A_CH + 2*B_CH), BK=32
    constexpr int SM128 = 3 * (2 * 128 * 64 + 2 * 128 * 64);  // 98304
    constexpr int SM96  = 3 * (2 * 128 * 64 + 2 * 96 * 64);   // 86016
    constexpr int SM32  = 3 * (2 * 128 * 64 + 2 * 32 * 64);   // 61440
    cudaFuncSetAttribute((const void*)hmma_gemm<128, 256, true, true, 2>,
                         cudaFuncAttributeMaxDynamicSharedMemorySize, SM128);
    cudaFuncSetAttribute((const void*)hmma_gemm<128, 256, true, false, 2>,
                         cudaFuncAttributeMaxDynamicSharedMemorySize, SM128);
    cudaFuncSetAttribute((const void*)hmma_gemm<96, 96, false, false, 2>,
                         cudaFuncAttributeMaxDynamicSharedMemorySize, SM96);
    cudaFuncSetAttribute((const void*)hmma_gemm<32, 32, false, false, 3>,
                         cudaFuncAttributeMaxDynamicSharedMemorySize, SM32);

    const int MB = E_EDGES / 128;  // 3125 row tiles

    prep_fold<<<1, 256>>>(W2, Wqk, Wk);
    prep_transpose_split<<<256, 256>>>(W0, W1);
    cudaMemsetAsync(d_out, 0, (size_t)out_size * sizeof(float));

    // ---- source branch: only q survives ----
    hmma_gemm<128, 256, true, true, 2><<<dim3(MB, 2), 256, SM128>>>(
        source_attr, nullptr, w0h, w0l, hiB, loB);
    hmma_gemm<128, 256, true, false, 2><<<dim3(MB, 2), 256, SM128>>>(
        hiB, loB, w1h, w1l, hiA, loA);
    hmma_gemm< 32,  32, false, false, 3><<<dim3(MB, 1), 256, SM32>>>(
        hiA, loA, w2qh, w2ql, qbuf, nullptr);

    // ---- neighbor branch: [x_neighbor(64) | k(32)] fused as N=96 ----
    hmma_gemm<128, 256, true, true, 2><<<dim3(MB, 2), 256, SM128>>>(
        neighbor_attr, nullptr, w0h, w0l, hiB, loB);
    hmma_gemm<128, 256, true, false, 2><<<dim3(MB, 2), 256, SM128>>>(
        hiB, loB, w1h, w1l, hiA, loA);
    hmma_gemm< 96,  96, false, false, 2><<<dim3(MB, 1), 256, SM96>>>(
        hiA, loA, wch, wcl, xnk, nullptr);

    // ---- attention + segment scatter ----
    edge_finalize<<<(E_EDGES * 32 + 255) / 256, 256>>>(ppr_scores, ppr_idx, out);
}

// round 13
// speedup vs baseline: 1.0831x; 1.0831x over previous
#include <cuda_runtime.h>
#include <cuda_bf16.h>
#include <math.h>
#include <stdint.h>

#define E_EDGES 400000
#define NGROUPS 25000

// ===========================================================================
// PTX helpers (sm_80-class only — toolchain targets plain sm_103, no tcgen05)
// ===========================================================================
__device__ __forceinline__ uint32_t smem_u32(const void* p) {
    uint32_t a;
    asm("{ .reg .u64 t; cvta.to.shared.u64 t, %1; cvt.u32.u64 %0, t; }"
        : "=r"(a) : "l"(p));
    return a;
}

#define CP_ASYNC16(sm, gm) \
    asm volatile("cp.async.cg.shared.global [%0], [%1], 16;" \
        :: "r"(sm), "l"(gm) : "memory")
#define CP_COMMIT() asm volatile("cp.async.commit_group;" ::: "memory")
#define CP_WAIT(n)  asm volatile("cp.async.wait_group %0;" :: "n"(n) : "memory")

__device__ __forceinline__ void ldsm_x4(uint32_t* d, uint32_t addr) {
    asm volatile("ldmatrix.sync.aligned.m8n8.x4.shared.b16 {%0,%1,%2,%3}, [%4];"
        : "=r"(d[0]), "=r"(d[1]), "=r"(d[2]), "=r"(d[3]) : "r"(addr));
}

#define MMA16816(d, a, b) \
    asm volatile("mma.sync.aligned.m16n8k16.row.col.f32.bf16.bf16.f32 " \
        "{%0,%1,%2,%3}, {%4,%5,%6,%7}, {%8,%9}, {%0,%1,%2,%3};" \
        : "+f"((d)[0]), "+f"((d)[1]), "+f"((d)[2]), "+f"((d)[3]) \
        : "r"((a)[0]), "r"((a)[1]), "r"((a)[2]), "r"((a)[3]), \
          "r"((b)[0]), "r"((b)[1]))

// SW64 swizzle for 64-byte rows (BK=32 bf16)
__device__ __forceinline__ uint32_t sw(uint32_t off) {
    return off ^ ((off >> 3) & 0x30);
}

// ===========================================================================
// Scratch globals (no cudaMalloc allowed)
// ===========================================================================
__device__ __nv_bfloat16 g_hiB[(size_t)E_EDGES * 256];
__device__ __nv_bfloat16 g_loB[(size_t)E_EDGES * 256];
// fused layer-3 partial outputs (per y-tile, summed in edge_finalize)
__device__ float g_q0  [(size_t)E_EDGES * 32];
__device__ float g_q1  [(size_t)E_EDGES * 32];
__device__ float g_xnk0[(size_t)E_EDGES * 96];
__device__ float g_xnk1[(size_t)E_EDGES * 96];

__device__ float g_W2q [256 * 32];   // W2 @ Wqk  (fp32, [k][n])
__device__ float g_Wcat[256 * 96];   // [W2 | W2@Wk] (fp32, [k][n])
// Transposed + split weights, [n][k] layout (K contiguous)
__device__ __nv_bfloat16 g_W0t_hi[256 * 256], g_W0t_lo[256 * 256];
__device__ __nv_bfloat16 g_W1t_hi[256 * 256], g_W1t_lo[256 * 256];
__device__ __nv_bfloat16 g_W2qt_hi[32 * 256], g_W2qt_lo[32 * 256];
__device__ __nv_bfloat16 g_Wct_hi[96 * 256],  g_Wct_lo[96 * 256];

__device__ __forceinline__ void split2(float v, __nv_bfloat16& h, __nv_bfloat16& l) {
    h = __float2bfloat16_rn(v);
    l = __float2bfloat16_rn(v - __bfloat162float(h));
}

// ===========================================================================
// prep1: fold head projections: g_W2q = W2@Wqk, g_Wcat = [W2 | W2@Wk]
// ===========================================================================
__global__ void prep_fold(const float* __restrict__ W2,
                          const float* __restrict__ Wqk,
                          const float* __restrict__ Wk) {
    __shared__ float sQ[64 * 32];
    __shared__ float sK[64 * 32];
    int tid = threadIdx.x;
    for (int i = tid; i < 64 * 32; i += 256) { sQ[i] = Wqk[i]; sK[i] = Wk[i]; }
    __syncthreads();
    int r = tid;
    float w2r[64];
#pragma unroll
    for (int j = 0; j < 64; ++j) w2r[j] = W2[r * 64 + j];
#pragma unroll 4
    for (int c = 0; c < 32; ++c) {
        float aq = 0.f, ak = 0.f;
#pragma unroll
        for (int j = 0; j < 64; ++j) {
            aq = fmaf(w2r[j], sQ[j * 32 + c], aq);
            ak = fmaf(w2r[j], sK[j * 32 + c], ak);
        }
        g_W2q[r * 32 + c]       = aq;
        g_Wcat[r * 96 + 64 + c] = ak;
    }
#pragma unroll
    for (int j = 0; j < 64; ++j) g_Wcat[r * 96 + j] = w2r[j];
}

// ===========================================================================
// prep2: transpose to [n][k] and split all GEMM weights to bf16 hi/lo
// ===========================================================================
__global__ void prep_transpose_split(const float* __restrict__ W0,
                                     const float* __restrict__ W1) {
    int t = blockIdx.x * 256 + threadIdx.x;
    int o = t >> 8, i = t & 255;
    __nv_bfloat16 h, l;
    split2(W0[i * 256 + o], h, l);  g_W0t_hi[t] = h;  g_W0t_lo[t] = l;
    split2(W1[i * 256 + o], h, l);  g_W1t_hi[t] = h;  g_W1t_lo[t] = l;
    if (o < 32) { split2(g_W2q[i * 32 + o], h, l);  g_W2qt_hi[t] = h; g_W2qt_lo[t] = l; }
    if (o < 96) { split2(g_Wcat[i * 96 + o], h, l); g_Wct_hi[t] = h;  g_Wct_lo[t] = l; }
}

// ===========================================================================
// HMMA GEMM, bf16x3: C = Ah*Bh + Al*Bh + Ah*Bl.
// BM=128, BN=128, BK=32, 8 K-chunks, 3 smem stages, one barrier/chunk.
// 256 threads = 8 warps (4M x 2N); each warp = 32 rows x 64 cols (NB=8 n8-tiles).
//
// FP32A:      A fp32 in gmem; LDG prefetch + in-register split + STS.
// SPLIT_RELU: epilogue = relu + re-split hi/lo bf16, width 256 (feeds L2).
// N3 > 0:     FUSED LAYER-3 epilogue. Full H2 tile (128x128 fp32 in acc) is
//             relu'd + split hi/lo into smem (4 K-chunks of 32, 64 KB), then
//             multiplied by the CTA's 128-col K-slice of W3t[N3,256] (bf16x3,
//             loaded serially in two K-halves). fp32 partial [128,N3] goes to
//             out0 (blockIdx.y=0) / out1 (y=1). H2 never touches gmem.
// ===========================================================================
template <bool SPLIT_RELU, int N3, bool FP32A>
__global__ void __launch_bounds__(256, 2)
hmma_gemm(const void* __restrict__ Ah_, const __nv_bfloat16* __restrict__ Al,
          const __nv_bfloat16* __restrict__ Bh, const __nv_bfloat16* __restrict__ Bl,
          const __nv_bfloat16* __restrict__ W3h, const __nv_bfloat16* __restrict__ W3l,
          void* __restrict__ out0, void* __restrict__ out1) {
    constexpr int BN    = 128;
    constexpr int NB    = 8;                 // n8-tiles per warp = 64 cols
    constexpr int A_CH  = 128 * 64;          // bytes per A split per chunk
    constexpr int B_CH  = BN * 64;
    constexpr int STAGE = 2 * A_CH + 2 * B_CH;   // 32 KB

    extern __shared__ char smem[];
    const uint32_t s0 = smem_u32(smem);

    const int tid  = threadIdx.x;
    const int lane = tid & 31;
    const int wid  = tid >> 5;
    const int m0w  = (wid & 3) * 32;
    const int n0w  = (wid >> 2) * 64;
    const int row0 = blockIdx.x * 128;
    const int col0 = blockIdx.y * BN;

    const float* Afp = (const float*)Ah_;
    const __nv_bfloat16* Ah = (const __nv_bfloat16*)Ah_;

    float acc[2][NB][4];
#pragma unroll
    for (int mi = 0; mi < 2; ++mi)
#pragma unroll
        for (int ni = 0; ni < NB; ++ni)
#pragma unroll
            for (int v = 0; v < 4; ++v) acc[mi][ni][v] = 0.f;

    float4 pf[4];  // FP32A prefetch

    auto loadB = [&](int c, int buf) {
        const int kk = c << 5;
#pragma unroll
        for (int i = tid; i < 2 * BN * 4; i += 256) {
            int sp = i / (BN * 4), idx = i % (BN * 4), n = idx >> 2, g = idx & 3;
            const __nv_bfloat16* src =
                (sp ? Bl : Bh) + (size_t)(col0 + n) * 256 + kk + g * 8;
            CP_ASYNC16(s0 + buf * STAGE + 2 * A_CH + sp * B_CH + sw(n * 64 + g * 16), src);
        }
    };
    auto loadA_cp = [&](int c, int buf) {
        const int kk = c << 5;
#pragma unroll
        for (int i = tid; i < 1024; i += 256) {
            int sp = i >> 9, idx = i & 511, r = idx >> 2, g = idx & 3;
            const __nv_bfloat16* src =
                (sp ? Al : Ah) + (size_t)(row0 + r) * 256 + kk + g * 8;
            CP_ASYNC16(s0 + buf * STAGE + sp * A_CH + sw(r * 64 + g * 16), src);
        }
    };
    auto ldA_f32 = [&](int c) {
        const int kk = c << 5;
#pragma unroll
        for (int j = 0; j < 4; ++j) {
            int f4 = tid + 256 * j;
            int r = f4 >> 3, c4 = f4 & 7;
            pf[j] = *(const float4*)(Afp + (size_t)(row0 + r) * 256 + kk + c4 * 4);
        }
    };
    auto stA_f32 = [&](int buf) {
#pragma unroll
        for (int j = 0; j < 4; ++j) {
            int f4 = tid + 256 * j;
            int r = f4 >> 3, c4 = f4 & 7;
            __nv_bfloat16 h0, l0, h1, l1, h2, l2, h3, l3;
            split2(pf[j].x, h0, l0); split2(pf[j].y, h1, l1);
            split2(pf[j].z, h2, l2); split2(pf[j].w, h3, l3);
            uint2 hw = make_uint2(
                (uint32_t)__bfloat16_as_ushort(h0) | ((uint32_t)__bfloat16_as_ushort(h1) << 16),
                (uint32_t)__bfloat16_as_ushort(h2) | ((uint32_t)__bfloat16_as_ushort(h3) << 16));
            uint2 lw = make_uint2(
                (uint32_t)__bfloat16_as_ushort(l0) | ((uint32_t)__bfloat16_as_ushort(l1) << 16),
                (uint32_t)__bfloat16_as_ushort(l2) | ((uint32_t)__bfloat16_as_ushort(l3) << 16));
            uint32_t off = buf * STAGE + sw(r * 64 + c4 * 8);
            *(uint2*)(smem + off)        = hw;
            *(uint2*)(smem + off + A_CH) = lw;
        }
    };

    // ---- prologue: stage chunks 0 and 1 ----
    if (FP32A) {
        ldA_f32(0); stA_f32(0);
        ldA_f32(1); stA_f32(1);
        loadB(0, 0); CP_COMMIT();
        loadB(1, 1); CP_COMMIT();
    } else {
        loadA_cp(0, 0); loadB(0, 0); CP_COMMIT();
        loadA_cp(1, 1); loadB(1, 1); CP_COMMIT();
    }

#pragma unroll 1
    for (int c = 0; c < 8; ++c) {
        if (c < 7) CP_WAIT(1); else CP_WAIT(0);
        __syncthreads();

        if (c < 6) {
            const int buf2 = (c + 2) % 3;
            if (FP32A) {
                ldA_f32(c + 2);
                loadB(c + 2, buf2);
            } else {
                loadA_cp(c + 2, buf2);
                loadB(c + 2, buf2);
            }
            CP_COMMIT();
        }

        const uint32_t st = s0 + (c % 3) * STAGE;
        const uint32_t da = st;
        const uint32_t db = st + 2 * A_CH;
#pragma unroll
        for (int ks = 0; ks < 2; ++ks) {
            uint32_t ah[2][4], al[2][4];
#pragma unroll
            for (int mi = 0; mi < 2; ++mi) {
                uint32_t aoff = sw((m0w + mi * 16 + (lane & 15)) * 64 +
                                   ks * 32 + (lane >> 4) * 16);
                ldsm_x4(ah[mi], da + aoff);
                ldsm_x4(al[mi], da + A_CH + aoff);
            }
            uint32_t bh[NB][2], bl[NB][2];
#pragma unroll
            for (int np = 0; np < NB / 2; ++np) {
                uint32_t boff = sw((n0w + np * 16 + (lane >> 4) * 8 + (lane & 7)) * 64 +
                                   ks * 32 + ((lane >> 3) & 1) * 16);
                ldsm_x4(&bh[2 * np][0], db + boff);
                ldsm_x4(&bl[2 * np][0], db + B_CH + boff);
            }
            // full product-major: acc reuse distance = 16 independent MMAs
#pragma unroll
            for (int mi = 0; mi < 2; ++mi)
#pragma unroll
                for (int ni = 0; ni < NB; ++ni)
                    MMA16816(acc[mi][ni], ah[mi], bh[ni]);
#pragma unroll
            for (int mi = 0; mi < 2; ++mi)
#pragma unroll
                for (int ni = 0; ni < NB; ++ni)
                    MMA16816(acc[mi][ni], al[mi], bh[ni]);
#pragma unroll
            for (int mi = 0; mi < 2; ++mi)
#pragma unroll
                for (int ni = 0; ni < NB; ++ni)
                    MMA16816(acc[mi][ni], ah[mi], bl[ni]);
        }
        if (FP32A && c < 6) stA_f32((c + 2) % 3);
    }

    // =======================================================================
    // Epilogues (compile-time selected)
    // =======================================================================
    if constexpr (SPLIT_RELU) {
        const int rbase = row0 + m0w + (lane >> 2);
        __nv_bfloat16* hi = (__nv_bfloat16*)out0;
        __nv_bfloat16* lo = (__nv_bfloat16*)out1;
#pragma unroll
        for (int mi = 0; mi < 2; ++mi) {
            const int r0 = rbase + mi * 16;
#pragma unroll
            for (int ni = 0; ni < NB; ++ni) {
                const int c = col0 + n0w + ni * 8 + (lane & 3) * 2;
#pragma unroll
                for (int h = 0; h < 2; ++h) {
                    float v0 = fmaxf(acc[mi][ni][2 * h],     0.f);
                    float v1 = fmaxf(acc[mi][ni][2 * h + 1], 0.f);
                    __nv_bfloat16 h0, l0, h1, l1;
                    split2(v0, h0, l0);
                    split2(v1, h1, l1);
                    size_t off = (size_t)(r0 + h * 8) * 256 + c;
                    *(uint32_t*)(hi + off) = (uint32_t)__bfloat16_as_ushort(h0) |
                                             ((uint32_t)__bfloat16_as_ushort(h1) << 16);
                    *(uint32_t*)(lo + off) = (uint32_t)__bfloat16_as_ushort(l0) |
                                             ((uint32_t)__bfloat16_as_ushort(l1) << 16);
                }
            }
        }
    }

    if constexpr (N3 > 0) {
        // ---- fused layer-3: G = relu(H2_tile) @ W3t[:, col0:col0+128]^T ----
        constexpr int NT3   = N3 / 8;        // n8-tiles per warp (warp spans all N3)
        constexpr int PH_SZ = 128 * 64;      // one K=32 chunk of P per split (8 KB)
        const uint32_t pH = s0;              // 4 chunks: 32 KB
        const uint32_t pL = s0 + 4 * PH_SZ;  // 4 chunks: 32 KB
        const uint32_t wH = s0 + 8 * PH_SZ;  // 2 W3 chunks hi
        const uint32_t wL = wH + 2 * N3 * 64;

        __syncthreads();   // all mainloop smem reads finished; smem is free

        // stage FULL P tile (this warp's 64 cols, all 128 rows it owns)
#pragma unroll
        for (int mi = 0; mi < 2; ++mi)
#pragma unroll
            for (int ni = 0; ni < NB; ++ni) {
                const int cl = n0w + ni * 8 + (lane & 3) * 2;  // col within 128
                const int j  = cl >> 5;
                const int cc = cl & 31;
#pragma unroll
                for (int rr = 0; rr < 2; ++rr) {
                    const int r = m0w + mi * 16 + (lane >> 2) + rr * 8;
                    float v0 = fmaxf(acc[mi][ni][2 * rr],     0.f);
                    float v1 = fmaxf(acc[mi][ni][2 * rr + 1], 0.f);
                    __nv_bfloat16 h0, l0, h1, l1;
                    split2(v0, h0, l0);
                    split2(v1, h1, l1);
                    uint32_t off = j * PH_SZ + sw(r * 64 + cc * 2);
                    *(uint32_t*)(smem + off) =
                        (uint32_t)__bfloat16_as_ushort(h0) |
                        ((uint32_t)__bfloat16_as_ushort(h1) << 16);
                    *(uint32_t*)(smem + 4 * PH_SZ + off) =
                        (uint32_t)__bfloat16_as_ushort(l0) |
                        ((uint32_t)__bfloat16_as_ushort(l1) << 16);
                }
            }

        float acc2[NT3][4];
#pragma unroll
        for (int ni = 0; ni < NT3; ++ni)
#pragma unroll
            for (int v = 0; v < 4; ++v) acc2[ni][v] = 0.f;

#pragma unroll 1
        for (int half = 0; half < 2; ++half) {
            if (half == 1) __syncthreads();  // all ldsm reads of wH/wL done

            // load W3 slice: K-chunks kc = 2*half, 2*half+1, both splits
            for (int i = tid; i < 4 * N3 * 4; i += 256) {
                int sp = i / (2 * N3 * 4), idx = i % (2 * N3 * 4);
                int j2 = idx / (N3 * 4), idx2 = idx % (N3 * 4);
                int n = idx2 >> 2, g = idx2 & 3;
                const int kc = 2 * half + j2;
                const __nv_bfloat16* src =
                    (sp ? W3l : W3h) + (size_t)n * 256 + col0 + kc * 32 + g * 8;
                CP_ASYNC16((sp ? wL : wH) + j2 * N3 * 64 + sw(n * 64 + g * 16), src);
            }
            CP_COMMIT();
            CP_WAIT(0);
            __syncthreads();   // W3 visible; (half 0) P stores visible to all

#pragma unroll
            for (int j2 = 0; j2 < 2; ++j2) {
                const int jg = 2 * half + j2;   // global P chunk
#pragma unroll
                for (int ks2 = 0; ks2 < 2; ++ks2) {
                    uint32_t ph4[4], pl4[4];
                    uint32_t aoff = jg * PH_SZ +
                                    sw((wid * 16 + (lane & 15)) * 64 +
                                       ks2 * 32 + (lane >> 4) * 16);
                    ldsm_x4(ph4, pH + aoff);
                    ldsm_x4(pl4, pL + aoff);
                    uint32_t w3h[NT3][2], w3l[NT3][2];
#pragma unroll
                    for (int np2 = 0; np2 < NT3 / 2; ++np2) {
                        uint32_t boff = j2 * N3 * 64 +
                                        sw((np2 * 16 + (lane >> 4) * 8 + (lane & 7)) * 64 +
                                           ks2 * 32 + ((lane >> 3) & 1) * 16);
                        ldsm_x4(&w3h[2 * np2][0], wH + boff);
                        ldsm_x4(&w3l[2 * np2][0], wL + boff);
                    }
#pragma unroll
                    for (int ni = 0; ni < NT3; ++ni) MMA16816(acc2[ni], ph4, w3h[ni]);
#pragma unroll
                    for (int ni = 0; ni < NT3; ++ni) MMA16816(acc2[ni], pl4, w3h[ni]);
#pragma unroll
                    for (int ni = 0; ni < NT3; ++ni) MMA16816(acc2[ni], ph4, w3l[ni]);
                }
            }
        }

        // store fp32 partial [128, N3] to the per-y buffer
        float* op = (float*)(blockIdx.y ? out1 : out0);
        const int r0 = row0 + wid * 16 + (lane >> 2);
#pragma unroll
        for (int ni = 0; ni < NT3; ++ni) {
            const int c = ni * 8 + (lane & 3) * 2;
            *(float2*)(op + (size_t)r0 * N3 + c) =
                make_float2(acc2[ni][0], acc2[ni][1]);
            *(float2*)(op + (size_t)(r0 + 8) * N3 + c) =
                make_float2(acc2[ni][2], acc2[ni][3]);
        }
    }
}

// ===========================================================================
// Edge finalize: one warp per edge. Sums the two layer-3 partials.
//   q = q0+q1; [xn|k] = xnk0+xnk1
//   s = sigmoid(dot(q,k)) * ppr;  atomicAdd(out[ppr_idx][:], xn[:] * s)
// ===========================================================================
__global__ void edge_finalize(const float* __restrict__ ppr_scores,
                              const int* __restrict__ ppr_idx,
                              float* __restrict__ out) {
    int gtid = blockIdx.x * blockDim.x + threadIdx.x;
    int edge = gtid >> 5;
    int lane = gtid & 31;
    if (edge >= E_EDGES) return;

    const float* x0 = g_xnk0 + (size_t)edge * 96;
    const float* x1 = g_xnk1 + (size_t)edge * 96;
    float qv = g_q0[(size_t)edge * 32 + lane] + g_q1[(size_t)edge * 32 + lane];
    float kv = x0[64 + lane] + x1[64 + lane];
    float p  = qv * kv;
#pragma unroll
    for (int off = 16; off > 0; off >>= 1)
        p += __shfl_xor_sync(0xffffffffu, p, off);

    float s = ppr_scores[edge] / (1.f + expf(-p));
    int g = ppr_idx[edge];
    float v0 = (x0[lane]      + x1[lane])      * s;
    float v1 = (x0[32 + lane] + x1[32 + lane]) * s;
    atomicAdd(&out[(size_t)g * 64 + lane],      v0);
    atomicAdd(&out[(size_t)g * 64 + 32 + lane], v1);
}

// ===========================================================================
// Launch sequence (graph-capturable)
// ===========================================================================
extern "C" void kernel_launch(void* const* d_in, const int* in_sizes, int n_in,
                              void* d_out, int out_size) {
    const float* source_attr   = (const float*)d_in[0];
    const float* neighbor_attr = (const float*)d_in[1];
    const float* ppr_scores    = (const float*)d_in[2];
    const int*   ppr_idx       = (const int*)  d_in[3];
    const float* W0  = (const float*)d_in[5];
    const float* W1  = (const float*)d_in[6];
    const float* W2  = (const float*)d_in[7];
    const float* Wqk = (const float*)d_in[8];
    const float* Wk  = (const float*)d_in[9];
    float* out = (float*)d_out;

    __nv_bfloat16 *hiB, *loB;
    __nv_bfloat16 *w0h, *w0l, *w1h, *w1l, *w2qh, *w2ql, *wch, *wcl;
    float *q0, *q1, *x0, *x1;
    cudaGetSymbolAddress((void**)&hiB, g_hiB);
    cudaGetSymbolAddress((void**)&loB, g_loB);
    cudaGetSymbolAddress((void**)&q0, g_q0);
    cudaGetSymbolAddress((void**)&q1, g_q1);
    cudaGetSymbolAddress((void**)&x0, g_xnk0);
    cudaGetSymbolAddress((void**)&x1, g_xnk1);
    cudaGetSymbolAddress((void**)&w0h, g_W0t_hi);
    cudaGetSymbolAddress((void**)&w0l, g_W0t_lo);
    cudaGetSymbolAddress((void**)&w1h, g_W1t_hi);
    cudaGetSymbolAddress((void**)&w1l, g_W1t_lo);
    cudaGetSymbolAddress((void**)&w2qh, g_W2qt_hi);
    cudaGetSymbolAddress((void**)&w2ql, g_W2qt_lo);
    cudaGetSymbolAddress((void**)&wch, g_Wct_hi);
    cudaGetSymbolAddress((void**)&wcl, g_Wct_lo);

    // dynamic smem: 3 stages x 32KB; fused epilogue reuses 64KB P + <=25KB W3
    constexpr int SMB = 3 * (2 * 128 * 64 + 2 * 128 * 64);  // 98304
    cudaFuncSetAttribute((const void*)hmma_gemm<true, 0, true>,
                         cudaFuncAttributeMaxDynamicSharedMemorySize, SMB);
    cudaFuncSetAttribute((const void*)hmma_gemm<false, 32, false>,
                         cudaFuncAttributeMaxDynamicSharedMemorySize, SMB);
    cudaFuncSetAttribute((const void*)hmma_gemm<false, 96, false>,
                         cudaFuncAttributeMaxDynamicSharedMemorySize, SMB);

    const int MB = E_EDGES / 128;  // 3125 row tiles

    prep_fold<<<1, 256>>>(W2, Wqk, Wk);
    prep_transpose_split<<<256, 256>>>(W0, W1);
    cudaMemsetAsync(d_out, 0, (size_t)out_size * sizeof(float));

    // ---- source branch: L1 (fp32 in -> H1 hi/lo), L2+L3 fused -> q partials ----
    hmma_gemm<true, 0, true><<<dim3(MB, 2), 256, SMB>>>(
        source_attr, nullptr, w0h, w0l, nullptr, nullptr, hiB, loB);
    hmma_gemm<false, 32, false><<<dim3(MB, 2), 256, SMB>>>(
        hiB, loB, w1h, w1l, w2qh, w2ql, q0, q1);

    // ---- neighbor branch: L2+L3 fused -> [xn|k] partials ----
    hmma_gemm<true, 0, true><<<dim3(MB, 2), 256, SMB>>>(
        neighbor_attr, nullptr, w0h, w0l, nullptr, nullptr, hiB, loB);
    hmma_gemm<false, 96, false><<<dim3(MB, 2), 256, SMB>>>(
        hiB, loB, w1h, w1l, wch, wcl, x0, x1);

    // ---- attention + segment scatter ----
    edge_finalize<<<(E_EDGES * 32 + 255) / 256, 256>>>(ppr_scores, ppr_idx, out);
}